// round 15
// baseline (speedup 1.0000x reference)
#include <cuda_runtime.h>
#include <cstddef>

#define KCODES 1024
#define DDIM   256
#define NPIX   65536
#define THREADS 256
#define MARGIN  7.5e-5f
#define CAND_SLACK 2e-4f

// ---- main kernel geometry ----
#define BPW 128      // pixels per block
#define TKW 256      // codes per tile (4 tiles; e staged exactly once)
#define DCW 32       // d per chunk
#define SE  260      // e_s row stride in floats (mult of 4)
#define CHUNK_F (DCW * SE)               // 8320 floats per buffer

// smem: z (32768 f) | e 2 buffers (16640 f) | en (1024 f) | A (128 f)
#define ZW_OFF   0
#define E_OFF    32768
#define ENW_OFF  (32768 + 2 * CHUNK_F)   // 49408
#define AW_OFF   (ENW_OFF + 1024)        // 50432
#define SMEMW_FLOATS (AW_OFF + 128)      // 50560 floats = 202,240 B

__device__ float g_enorm[KCODES];
__device__ float g_A[NPIX];
__device__ float g_bv[NPIX];
__device__ int   g_nflag;
__device__ int   g_flags[NPIX];

#define FMA2(a, x, y) \
    asm("fma.rn.f32x2 %0, %1, %2, %0;" : "+l"(a) : "l"(x), "l"(y))
#define DUP2(d, s) \
    asm("mov.b64 %0, {%1,%1};" : "=l"(d) : "f"(s))

// ---------------------------------------------------------------------------
// Emulated reference row sum-of-squares (proven exact R7-R14).
// ---------------------------------------------------------------------------
__device__ __forceinline__ float sumsq_emul(const float* x, long stride) {
    float S[8];
#pragma unroll
    for (int l = 0; l < 8; l++) S[l] = 0.f;
    for (int t = 0; t < DDIM / 8; t++) {
#pragma unroll
        for (int l = 0; l < 8; l++) {
            float v = x[(long)(8 * t + l) * stride];
            S[l] = __fadd_rn(S[l], __fmul_rn(v, v));
        }
    }
    float m0 = __fadd_rn(S[0], S[4]);
    float m1 = __fadd_rn(S[1], S[5]);
    float m2 = __fadd_rn(S[2], S[6]);
    float m3 = __fadd_rn(S[3], S[7]);
    return __fadd_rn(__fadd_rn(m0, m1), __fadd_rn(m2, m3));
}

__global__ void reset_kernel() { if (threadIdx.x == 0) g_nflag = 0; }

__global__ void enorm_kernel(const float* __restrict__ emb) {
    int c = blockIdx.x * blockDim.x + threadIdx.x;
    if (c < KCODES) g_enorm[c] = sumsq_emul(emb + (size_t)c * DDIM, 1);
}

__global__ void anorm_kernel(const float* __restrict__ z) {
    int p = blockIdx.x * blockDim.x + threadIdx.x;
    if (p < NPIX) {
        const float* zp = z + (size_t)(p >> 12) * (DDIM * 4096) + (p & 4095);
        g_A[p] = sumsq_emul(zp, 4096);
    }
}

// ---------------------------------------------------------------------------
// Main pass: 256 threads, 128 px/block, warp = 32 px x 128 codes,
// thread = 8 px x 16 codes (64 FMA2 per d per 96 B/lane smem -> fma-bound).
// Code-pair packed accs; z duplicated by movs; e read as natural u64 pairs.
// 4 code-tiles of 256; e staged exactly once, conflict-free, double-buffered.
// ---------------------------------------------------------------------------
__global__ __launch_bounds__(THREADS, 1)
void vq7(const float* __restrict__ z, const float* __restrict__ emb,
         float* __restrict__ out) {
    extern __shared__ float smem[];
    float* z_s  = smem + ZW_OFF;
    float* e_s  = smem + E_OFF;
    float* en_s = smem + ENW_OFF;
    float* A_s  = smem + AW_OFF;

    const int tid  = threadIdx.x;
    const int lane = tid & 31;
    const int w    = tid >> 5;          // 8 warps
    const int pxg  = lane & 3;          // 4 px-groups x 8 px = 32 px
    const int cg   = lane >> 2;         // 8 code-groups x 16 codes = 128
    const int band = w & 3;             // 4 px-bands of 32
    const int ccl  = w >> 2;            // 2 code-clusters of 128
    const int px0  = band * 32 + pxg * 8;   // this thread's 8 pixels
    const int cofs = ccl * 128 + cg * 16;   // 16 codes within tile

    const int n0 = blockIdx.x * BPW;
    const float* zbase = z + (size_t)(n0 >> 12) * (DDIM * 4096) + (n0 & 4095);

    // ---- z tile [256][128], coalesced ----
#pragma unroll
    for (int it = 0; it < 32; it++) {
        int idx = it * THREADS + tid;            // 8192 float4 slots
        int d = idx >> 5, c4 = (idx & 31) << 2;
        *(float4*)(z_s + d * BPW + c4) =
            *(const float4*)(zbase + (size_t)d * 4096 + c4);
    }
    for (int i = tid; i < KCODES; i += THREADS) en_s[i] = g_enorm[i];
    if (tid < BPW) A_s[tid] = g_A[n0 + tid];
    __syncthreads();

    float A8[8];
#pragma unroll
    for (int j = 0; j < 8; j++) A8[j] = A_s[px0 + j];

    float bv[8], sv[8]; int bi[8];
#pragma unroll
    for (int j = 0; j < 8; j++) { bv[j] = 3.4e38f; sv[j] = 3.4e38f; bi[j] = 0; }

    for (int k0 = 0; k0 < KCODES; k0 += TKW) {
        unsigned long long acc[8][8];   // 8 px x 8 code-pairs
#pragma unroll
        for (int i = 0; i < 8; i++)
#pragma unroll
            for (int c = 0; c < 8; c++) acc[i][c] = 0ull;

        // staging: thread owns one code (k0+tid), 32 d per chunk
        const float* erow = emb + (size_t)(k0 + tid) * DDIM;

        // prologue: load + store chunk 0 into buffer 0
        float4 st[8];
#pragma unroll
        for (int j = 0; j < 8; j++) st[j] = *(const float4*)(erow + 4 * j);
        {
            float* dst = e_s + tid;
#pragma unroll
            for (int j = 0; j < 8; j++) {
                dst[(4 * j + 0) * SE] = st[j].x;
                dst[(4 * j + 1) * SE] = st[j].y;
                dst[(4 * j + 2) * SE] = st[j].z;
                dst[(4 * j + 3) * SE] = st[j].w;
            }
        }
        __syncthreads();

        for (int ch = 0; ch < DDIM / DCW; ch++) {
            if (ch < DDIM / DCW - 1) {           // prefetch next chunk
                const float* er = erow + (ch + 1) * DCW;
#pragma unroll
                for (int j = 0; j < 8; j++) st[j] = *(const float4*)(er + 4 * j);
            }

            const float* eb = e_s + (ch & 1) * CHUNK_F + cofs;
            const float* zb = z_s + (size_t)(ch * DCW) * BPW + px0;
#pragma unroll 2
            for (int d = 0; d < DCW; d++) {
                float4 z0 = *(const float4*)(zb + (size_t)d * BPW);
                float4 z1 = *(const float4*)(zb + (size_t)d * BPW + 4);
                ulonglong2 e0 = *(const ulonglong2*)(eb + (size_t)d * SE);
                ulonglong2 e1 = *(const ulonglong2*)(eb + (size_t)d * SE + 4);
                ulonglong2 e2 = *(const ulonglong2*)(eb + (size_t)d * SE + 8);
                ulonglong2 e3 = *(const ulonglong2*)(eb + (size_t)d * SE + 12);
                unsigned long long ec[8] = {e0.x, e0.y, e1.x, e1.y,
                                            e2.x, e2.y, e3.x, e3.y};
                unsigned long long zd[8];
                DUP2(zd[0], z0.x); DUP2(zd[1], z0.y);
                DUP2(zd[2], z0.z); DUP2(zd[3], z0.w);
                DUP2(zd[4], z1.x); DUP2(zd[5], z1.y);
                DUP2(zd[6], z1.z); DUP2(zd[7], z1.w);
#pragma unroll
                for (int i = 0; i < 8; i++)
#pragma unroll
                    for (int c = 0; c < 8; c++)
                        FMA2(acc[i][c], zd[i], ec[c]);
            }

            if (ch < DDIM / DCW - 1) {           // store prefetched chunk
                float* dst = e_s + ((ch + 1) & 1) * CHUNK_F + tid;
#pragma unroll
                for (int j = 0; j < 8; j++) {
                    dst[(4 * j + 0) * SE] = st[j].x;
                    dst[(4 * j + 1) * SE] = st[j].y;
                    dst[(4 * j + 2) * SE] = st[j].z;
                    dst[(4 * j + 3) * SE] = st[j].w;
                }
            }
            __syncthreads();
        }

        // epilogue: acc[i][c] = codes (cofs+2c, cofs+2c+1) for pixel px0+i.
        // c ascending, lo before hi -> ascending k, strict '<' (first-index)
#pragma unroll
        for (int c = 0; c < 8; c++) {
            int klo = k0 + cofs + 2 * c;
            float enlo = en_s[klo], enhi = en_s[klo + 1];
#pragma unroll
            for (int i = 0; i < 8; i++) {
                float lo = __uint_as_float((unsigned)(acc[i][c] & 0xffffffffull));
                float hi = __uint_as_float((unsigned)(acc[i][c] >> 32));
                float dl = __fadd_rn(__fsub_rn(A8[i], __fmul_rn(2.0f, lo)), enlo);
                float dh = __fadd_rn(__fsub_rn(A8[i], __fmul_rn(2.0f, hi)), enhi);
                if (dl < bv[i]) { sv[i] = bv[i]; bv[i] = dl; bi[i] = klo; }
                else if (dl < sv[i]) sv[i] = dl;
                if (dh < bv[i]) { sv[i] = bv[i]; bv[i] = dh; bi[i] = klo + 1; }
                else if (dh < sv[i]) sv[i] = dh;
            }
        }
    }

    // ---- cross-thread merge: 16 contributors (ccl x cg) per pixel ----
    __syncthreads();
    float* rv = z_s;                     // reuse: [128][17]
    int*   ri = (int*)(z_s + 2176);
    float* rs = z_s + 4352;
    const int slot = ccl * 8 + cg;       // 0..15
#pragma unroll
    for (int j = 0; j < 8; j++) {
        int p = px0 + j;
        rv[p * 17 + slot] = bv[j];
        ri[p * 17 + slot] = bi[j];
        rs[p * 17 + slot] = sv[j];
    }
    __syncthreads();
    if (tid < BPW) {
        float b = rv[tid * 17]; int x0 = ri[tid * 17]; float s = rs[tid * 17];
#pragma unroll
        for (int t = 1; t < 16; t++) {
            float v = rv[tid * 17 + t]; int x = ri[tid * 17 + t];
            float s2 = rs[tid * 17 + t];
            if (v < b || (v == b && x < x0)) { s = fminf(b, s2); b = v; x0 = x; }
            else s = fminf(s, v);
        }
        out[n0 + tid]  = (float)x0;
        g_bv[n0 + tid] = b;
        if (__fsub_rn(s, b) < MARGIN) {
            int idx = atomicAdd(&g_nflag, 1);
            g_flags[idx] = n0 + tid;
        }
    }
}

// ---------------------------------------------------------------------------
// Fixup: fp32 screening (4 interleaved chains), then DF-exact dots on
// candidates only (validated R11-R14).
// ---------------------------------------------------------------------------
#define FTH 256
#define FPX 16
#define MAXC 32

__device__ __forceinline__ float df_dist(const float* zcol, const float* er,
                                         float A, float en) {
    float hi = 0.f, lo = 0.f;
    for (int d = 0; d < DDIM; d++) {
        float x = zcol[d * FPX], y = er[d];
        float pm = __fmul_rn(x, y);
        float e1 = fmaf(x, y, -pm);
        float t  = __fadd_rn(hi, pm);
        float v  = __fsub_rn(t, hi);
        float e2 = __fadd_rn(__fsub_rn(hi, __fsub_rn(t, v)), __fsub_rn(pm, v));
        hi = t;
        lo = __fadd_rn(lo, __fadd_rn(e1, e2));
    }
    float M = __fadd_rn(hi, lo);
    return __fadd_rn(__fsub_rn(A, __fmul_rn(2.0f, M)), en);
}

__global__ __launch_bounds__(FTH)
void fixup3(const float* __restrict__ z, const float* __restrict__ emb,
            float* __restrict__ out) {
    __shared__ float z_s[DDIM * FPX];
    __shared__ float en_s[KCODES];
    __shared__ float A_s[FPX], bv_s[FPX];
    __shared__ int   pl_s[FPX], ccnt[FPX];
    __shared__ int   cand[FPX][MAXC];

    const int tid = threadIdx.x;
    for (int i = tid; i < KCODES; i += FTH) en_s[i] = g_enorm[i];

    for (int base = blockIdx.x * FPX; base < g_nflag; base += gridDim.x * FPX) {
        int nhere = g_nflag - base; if (nhere > FPX) nhere = FPX;
        __syncthreads();
        if (tid < FPX) {
            int p = g_flags[base + (tid < nhere ? tid : 0)];
            pl_s[tid] = p;
            A_s[tid]  = g_A[p];
            bv_s[tid] = g_bv[p];
            ccnt[tid] = 0;
        }
        __syncthreads();
        for (int i = tid; i < DDIM * FPX; i += FTH) {
            int d = i >> 4, q = i & 15;
            int p = pl_s[q];
            z_s[i] = z[(size_t)(p >> 12) * (DDIM * 4096)
                       + (size_t)d * 4096 + (p & 4095)];
        }
        __syncthreads();

        {   // screening: 4 interleaved code chains per j
            int px = tid & 15, kg = tid >> 4;
            float A = A_s[px], thr = __fadd_rn(bv_s[px], CAND_SLACK);
            const float* zcol = z_s + px;
            for (int j = 0; j < 16; j++) {
                int kb = kg + 16 * j;
                const float* e0r = emb + (size_t)(kb      ) * DDIM;
                const float* e1r = emb + (size_t)(kb + 256) * DDIM;
                const float* e2r = emb + (size_t)(kb + 512) * DDIM;
                const float* e3r = emb + (size_t)(kb + 768) * DDIM;
                float a0 = 0.f, a1 = 0.f, a2 = 0.f, a3 = 0.f;
#pragma unroll 8
                for (int d = 0; d < DDIM; d++) {
                    float zv = zcol[d * FPX];
                    a0 = fmaf(zv, e0r[d], a0);
                    a1 = fmaf(zv, e1r[d], a1);
                    a2 = fmaf(zv, e2r[d], a2);
                    a3 = fmaf(zv, e3r[d], a3);
                }
                float dv[4] = {
                    __fadd_rn(__fsub_rn(A, __fmul_rn(2.0f, a0)), en_s[kb]),
                    __fadd_rn(__fsub_rn(A, __fmul_rn(2.0f, a1)), en_s[kb + 256]),
                    __fadd_rn(__fsub_rn(A, __fmul_rn(2.0f, a2)), en_s[kb + 512]),
                    __fadd_rn(__fsub_rn(A, __fmul_rn(2.0f, a3)), en_s[kb + 768])};
#pragma unroll
                for (int c = 0; c < 4; c++) {
                    if (dv[c] < thr) {
                        int s = atomicAdd(&ccnt[px], 1);
                        if (s < MAXC) cand[px][s] = kb + 256 * c;
                    }
                }
            }
        }
        __syncthreads();

        {   // DF phase: warp w handles px w, w+8
            int warp = tid >> 5, lane = tid & 31;
            for (int pp = warp; pp < FPX; pp += 8) {
                int cnt = ccnt[pp];
                const float* zcol = z_s + pp;
                float A = A_s[pp];
                float bb = 3.4e38f; int bk = KCODES;
                if (cnt <= MAXC) {
                    if (lane < cnt) {
                        int k = cand[pp][lane];
                        bb = df_dist(zcol, emb + (size_t)k * DDIM, A, en_s[k]);
                        bk = k;
                    }
                } else {
                    for (int k = lane; k < KCODES; k += 32) {
                        float dv = df_dist(zcol, emb + (size_t)k * DDIM, A, en_s[k]);
                        if (dv < bb || (dv == bb && k < bk)) { bb = dv; bk = k; }
                    }
                }
#pragma unroll
                for (int off = 16; off; off >>= 1) {
                    float ov = __shfl_xor_sync(0xffffffffu, bb, off);
                    int   ok = __shfl_xor_sync(0xffffffffu, bk, off);
                    if (ov < bb || (ov == bb && ok < bk)) { bb = ov; bk = ok; }
                }
                if (lane == 0 && pp < nhere) out[pl_s[pp]] = (float)bk;
            }
        }
    }
}

// ---------------------------------------------------------------------------
extern "C" void kernel_launch(void* const* d_in, const int* in_sizes, int n_in,
                              void* d_out, int out_size) {
    const float* z   = nullptr;
    const float* emb = nullptr;
    for (int i = 0; i < n_in; i++) {
        long s = (long)in_sizes[i];
        if (s == 16777216L || s == 67108864L)   z   = (const float*)d_in[i];
        else if (s == 262144L || s == 1048576L) emb = (const float*)d_in[i];
    }
    if (!z)   z   = (const float*)d_in[0];
    if (!emb) emb = (const float*)d_in[n_in > 1 ? 1 : 0];
    float* out = (float*)d_out;

    reset_kernel<<<1, 32>>>();
    enorm_kernel<<<32, 32>>>(emb);
    anorm_kernel<<<NPIX / 128, 128>>>(z);

    size_t smw = (size_t)SMEMW_FLOATS * sizeof(float);
    cudaFuncSetAttribute(vq7, cudaFuncAttributeMaxDynamicSharedMemorySize,
                         (int)smw);
    vq7<<<NPIX / BPW, THREADS, smw>>>(z, emb, out);
    fixup3<<<256, FTH>>>(z, emb, out);
}